// round 13
// baseline (speedup 1.0000x reference)
#include <cuda_runtime.h>
#include <cuda_bf16.h>
#include <math.h>

#define B_  8
#define T_  12
#define N_  256
#define H_  64
#define E_  16
#define TB_ (T_*B_)
#define NND ((size_t)65536)
static const size_t NN_ = (size_t)N_*N_;

// ---------------- static device scratch ----------------
__device__ float g_adj[N_*N_];
__device__ float g_S[TB_*2*N_*N_];          // (tb, slot{S, adj@S}, N, N)
__device__ float g_invd[TB_*N_];
__device__ float g_Wg0[256*132*128];
__device__ float g_Wu0[256*132*64];
__device__ float g_Wg1[256*256*128];
__device__ float g_Wu1[256*256*64];
__device__ float g_Bg0[256*128];
__device__ float g_Bu0[256*64];
__device__ float g_Bg1[256*128];
__device__ float g_Bu1[256*64];
__device__ float g_Ppa[TB_*2*256*64];       // sup @ (invd*pa_t)
__device__ float g_gx[8*2*256*64];          // x-part GEMM cols (per step scratch)
__device__ float g_zs[8*256*64];
__device__ float g_rbuf[8*256*64];
__device__ float g_state[8*256*64];
__device__ float g_seq0[8*12*256*64];

// ---------------- adj = softmax(relu(E E^T), axis=1) ----------------
__global__ __launch_bounds__(256) void adj_k(const float* __restrict__ E, float* __restrict__ adj) {
    __shared__ float sE[N_*E_];
    __shared__ float red[N_];
    int n = blockIdx.x, m = threadIdx.x;
    for (int i = m; i < N_*E_; i += 256) sE[i] = E[i];
    __syncthreads();
    float dot = 0.f;
    #pragma unroll
    for (int e = 0; e < E_; e++) dot += sE[n*E_+e] * sE[m*E_+e];
    float sc = fmaxf(dot, 0.f);
    red[m] = sc; __syncthreads();
    for (int s = 128; s > 0; s >>= 1) { if (m < s) red[m] = fmaxf(red[m], red[m+s]); __syncthreads(); }
    float mx = red[0]; __syncthreads();
    float ex = __expf(sc - mx);
    red[m] = ex; __syncthreads();
    for (int s = 128; s > 0; s >>= 1) { if (m < s) red[m] += red[m+s]; __syncthreads(); }
    adj[n*N_+m] = ex / red[0];
}

// ---------------- fused per-node weight expansion (all 4 pools) ----------------
__global__ __launch_bounds__(128) void wexpand_all(
    const float* __restrict__ E,
    const float* __restrict__ p0, const float* __restrict__ p1,
    const float* __restrict__ p2, const float* __restrict__ p3,
    float* __restrict__ w0, float* __restrict__ w1,
    float* __restrict__ w2, float* __restrict__ w3)
{
    __shared__ float sE[256][16];
    int tid = threadIdx.x;
    for (int i = tid; i < 256*16; i += 128) sE[i>>4][i&15] = E[i];
    __syncthreads();
    int which = blockIdx.y;
    int Cin  = (which < 2) ? 66 : 128;
    int Cout = (which & 1) ? 64 : 128;
    int Din  = (which < 2) ? 2 : 64;
    const float* pool = which==0?p0:which==1?p1:which==2?p2:p3;
    float* Wp         = which==0?w0:which==1?w1:which==2?w2:w3;
    int r = blockIdx.x;
    if (r >= 2*Cin) return;
    int o = tid;
    if (o >= Cout) return;
    int k = (r >= Cin) ? 1 : 0;
    int c = r - k*Cin;
    int i = (c < 64) ? (Din + c) : (c - 64);
    float pe[16];
    #pragma unroll
    for (int e = 0; e < 16; e++)
        pe[e] = pool[(((size_t)e*2 + k)*Cin + i)*Cout + o];
    size_t K2C = (size_t)2*Cin*Cout;
    float* outp = Wp + (size_t)r*Cout + o;
    for (int n = 0; n < 256; n++) {
        float4 a  = *(const float4*)&sE[n][0];
        float4 b  = *(const float4*)&sE[n][4];
        float4 cc = *(const float4*)&sE[n][8];
        float4 d  = *(const float4*)&sE[n][12];
        float acc = a.x*pe[0]+a.y*pe[1]+a.z*pe[2]+a.w*pe[3]
                  + b.x*pe[4]+b.y*pe[5]+b.z*pe[6]+b.w*pe[7]
                  + cc.x*pe[8]+cc.y*pe[9]+cc.z*pe[10]+cc.w*pe[11]
                  + d.x*pe[12]+d.y*pe[13]+d.z*pe[14]+d.w*pe[15];
        outp[(size_t)n*K2C] = acc;
    }
}

__global__ void bexpand_all(const float* __restrict__ E,
    const float* __restrict__ b0, const float* __restrict__ b1,
    const float* __restrict__ b2, const float* __restrict__ b3,
    float* __restrict__ o0, float* __restrict__ o1,
    float* __restrict__ o2, float* __restrict__ o3)
{
    int which = blockIdx.y;
    int Cout = (which & 1) ? 64 : 128;
    const float* bp = which==0?b0:which==1?b1:which==2?b2:b3;
    float* outp     = which==0?o0:which==1?o1:which==2?o2:o3;
    int n = blockIdx.x, o = threadIdx.x;
    if (o >= Cout) return;
    float acc = 0.f;
    #pragma unroll
    for (int e = 0; e < 16; e++) acc += E[n*16+e]*bp[e*Cout+o];
    outp[n*Cout+o] = acc;
}

// ---------------- S[tb,i,j] = exp(-L1(pa[b,t,i], pa[b,t,j])) ----------------
__global__ __launch_bounds__(256) void sker_k(const float* __restrict__ pa, float* __restrict__ S) {
    __shared__ float pi[64][68];
    __shared__ float pj[64][68];
    int tb = blockIdx.x;
    int t = tb >> 3, b = tb & 7;
    int i0 = blockIdx.y * 64;
    int tid = threadIdx.x;
    const float* pab = pa + (((size_t)b*T_ + t)*N_) * H_;
    for (int idx = tid; idx < 64*64; idx += 256) {
        int r = idx >> 6, h = idx & 63;
        pi[r][h] = pab[(size_t)(i0+r)*H_ + h];
    }
    float* Sb = S + (size_t)tb * 2 * NN_;
    int il = (tid >> 4) << 2;
    int jl = (tid & 15) << 2;
    for (int j0 = 0; j0 < N_; j0 += 64) {
        __syncthreads();
        for (int idx = tid; idx < 64*64; idx += 256) {
            int r = idx >> 6, h = idx & 63;
            pj[r][h] = pab[(size_t)(j0+r)*H_ + h];
        }
        __syncthreads();
        float d[4][4] = {};
        #pragma unroll
        for (int h = 0; h < 64; h += 4) {
            float4 a[4], c[4];
            #pragma unroll
            for (int q = 0; q < 4; q++) a[q] = *(const float4*)&pi[il+q][h];
            #pragma unroll
            for (int q = 0; q < 4; q++) c[q] = *(const float4*)&pj[jl+q][h];
            #pragma unroll
            for (int ii = 0; ii < 4; ii++)
                #pragma unroll
                for (int jj = 0; jj < 4; jj++)
                    d[ii][jj] += fabsf(a[ii].x-c[jj].x) + fabsf(a[ii].y-c[jj].y)
                               + fabsf(a[ii].z-c[jj].z) + fabsf(a[ii].w-c[jj].w);
        }
        #pragma unroll
        for (int ii = 0; ii < 4; ii++) {
            float4 v = make_float4(__expf(-d[ii][0]), __expf(-d[ii][1]),
                                   __expf(-d[ii][2]), __expf(-d[ii][3]));
            *(float4*)&Sb[(size_t)(i0+il+ii)*N_ + j0 + jl] = v;
        }
    }
}

__global__ void invd_k(const float* __restrict__ S, float* __restrict__ invd) {
    int tb = blockIdx.x, j = threadIdx.x;
    const float* Sb = S + (size_t)tb * 2 * NN_;
    float s = 0.f;
    #pragma unroll 8
    for (int i = 0; i < N_; i++) s += Sb[(size_t)i*N_ + j];
    invd[tb*N_ + j] = 1.f / s;
}

// ---------------- precompute SGEMM (R11 proven, double-buffered) ----------------
template<int KSPLIT, int XMAP>
__global__ __launch_bounds__(256) void gemm_k(
    const float* __restrict__ A, size_t aStride,
    const float* __restrict__ X, int ldx, size_t xStride,
    const float* __restrict__ invd, int ivStride,
    float* __restrict__ Y, int ldy, size_t yStride)
{
    __shared__ float As[2][16][68];
    __shared__ float Xs[2][16][64];
    const int KL = KSPLIT ? 128 : 256;
    int z = blockIdx.z;
    int b    = KSPLIT ? (z & 7) : z;
    int koff = KSPLIT ? ((z >> 3) * 128) : 0;
    const float* Az = A + (size_t)b * aStride + koff;
    const float* Xz;
    if (XMAP) {
        int t = z >> 3, bb = z & 7;
        Xz = X + ((size_t)(bb*T_ + t)) * N_ * ldx;
    } else {
        Xz = X + (size_t)b * xStride + (size_t)koff * ldx;
    }
    float* Yz = Y + (size_t)z * yStride;
    const float* iv = invd ? (invd + (size_t)(XMAP ? z : b) * ivStride + koff) : nullptr;
    int m0 = blockIdx.y * 64, c0 = blockIdx.x * 64;
    int tid = threadIdx.x;
    int tx = tid & 15, ty = tid >> 4;
    int a_m = tid >> 2, a_k = (tid & 3) * 4;
    int x_k = tid >> 4, x_c = (tid & 15) * 4;
    float acc[4][4] = {};

    float4 av = *(const float4*)&Az[(size_t)(m0 + a_m)*256 + a_k];
    float4 xv = *(const float4*)&Xz[(size_t)(x_k)*ldx + c0 + x_c];
    if (iv) { float s = iv[x_k]; xv.x *= s; xv.y *= s; xv.z *= s; xv.w *= s; }

    int cur = 0;
    for (int k0 = 0; k0 < KL; k0 += 16) {
        As[cur][a_k+0][a_m] = av.x; As[cur][a_k+1][a_m] = av.y;
        As[cur][a_k+2][a_m] = av.z; As[cur][a_k+3][a_m] = av.w;
        *(float4*)&Xs[cur][x_k][x_c] = xv;
        __syncthreads();
        if (k0 + 16 < KL) {
            av = *(const float4*)&Az[(size_t)(m0 + a_m)*256 + k0 + 16 + a_k];
            xv = *(const float4*)&Xz[(size_t)(k0 + 16 + x_k)*ldx + c0 + x_c];
            if (iv) { float s = iv[k0 + 16 + x_k]; xv.x *= s; xv.y *= s; xv.z *= s; xv.w *= s; }
        }
        #pragma unroll
        for (int kk = 0; kk < 16; kk++) {
            float4 a4 = *(const float4*)&As[cur][kk][ty*4];
            float4 x4 = *(const float4*)&Xs[cur][kk][tx*4];
            acc[0][0] += a4.x*x4.x; acc[0][1] += a4.x*x4.y; acc[0][2] += a4.x*x4.z; acc[0][3] += a4.x*x4.w;
            acc[1][0] += a4.y*x4.x; acc[1][1] += a4.y*x4.y; acc[1][2] += a4.y*x4.z; acc[1][3] += a4.y*x4.w;
            acc[2][0] += a4.z*x4.x; acc[2][1] += a4.z*x4.y; acc[2][2] += a4.z*x4.z; acc[2][3] += a4.z*x4.w;
            acc[3][0] += a4.w*x4.x; acc[3][1] += a4.w*x4.y; acc[3][2] += a4.w*x4.z; acc[3][3] += a4.w*x4.w;
        }
        cur ^= 1;
    }
    #pragma unroll
    for (int i = 0; i < 4; i++) {
        float4 v = make_float4(acc[i][0], acc[i][1], acc[i][2], acc[i][3]);
        *(float4*)&Yz[(size_t)(m0 + ty*4 + i)*ldy + c0 + tx*4] = v;
    }
}

// ================= fused per-node GEMM + MLP =================
// Block = 4 nodes, 256 threads = 8 b-groups x 32 c-groups.
// Phase 1: g[k][nj][b][c] = sum_m A_k[n,m]*iv[m]*X[b,m,c]  (X = [state|x] MODE0, zs MODE1)
// Phase 2: per-node MLP (o-major, 8-wide W prefetch) with fused GRU epilogue.
// MODE 0 (gate): sigmoid; o<64: zs = z*(state+pa); o>=64: rbuf = r; also writes gx (x-part cols)
// MODE 1 (upd):  tanh -> hc; s = r*(state+pa)+(1-r)*hc -> state, seq, (hid)
template<int CSP, int CSR, int COUT, int MODE>
__global__ __launch_bounds__(256) void fused_k(
    const float* __restrict__ Sb,      // S + t*8*2*NND
    const float* __restrict__ iv_t,    // invd + t*8*256
    const float* __restrict__ Xsrc,    // MODE0: state; MODE1: zs   [(b*256+m)*64+c]
    const float* __restrict__ xin,     // MODE0: x-part src (already + t offset)
    size_t xbs,                        // xin b-stride (elements)
    const float* __restrict__ Ppa_t,   // MODE0 only
    const float* __restrict__ W, const float* __restrict__ Bv,
    const float* __restrict__ sold,    // state for epilogue
    const float* __restrict__ pa_t,
    const float* __restrict__ rbuf_in, // MODE1
    const float* __restrict__ gx_in,   // MODE1: x-part MLP input
    float* __restrict__ gx_out,        // MODE0
    float* __restrict__ o1, float* __restrict__ o2, float* __restrict__ hid)
{
    constexpr int XLD = CSR - 64;      // x-part cols
    extern __shared__ float sm[];
    float* Xs = sm;                    // [2][8][8][CSP]
    float* As = Xs + 2*8*8*CSP;        // [2][8][8][8] = [buf][bb][m][k*4+nj]
    float* G  = As + 2*512;            // [8][4][2][CSP]
    float* In = G + 8*4*2*CSP;         // [8][2*CSR]
    int tid = threadIdx.x;
    int n0 = blockIdx.x << 2;
    int b = tid >> 5, cg = tid & 31;
    constexpr int NC4 = CSP/4;
    bool act = cg < NC4;
    int c4 = cg << 2;
    const float* ivb = iv_t + b*256;

    float acc[2][4][4];
    #pragma unroll
    for (int k = 0; k < 2; k++)
        #pragma unroll
        for (int j = 0; j < 4; j++)
            #pragma unroll
            for (int q = 0; q < 4; q++) acc[k][j][q] = 0.f;

    float4 xreg[8];
    float2 areg;
    int lin = tid*2;
    int la_m = lin & 7, la_nj = (lin>>3)&3, la_k = (lin>>5)&1, la_b = lin>>6;
    const float* arow = Sb + (size_t)la_b*2*NND + (size_t)la_k*NND + (size_t)(n0+la_nj)*256;

    #define LOADC(m0) do { \
        if (act) { \
            _Pragma("unroll") \
            for (int m = 0; m < 8; m++) { \
                float s = __ldg(ivb + (m0) + m); \
                float4 v; \
                if (MODE == 1 || c4 < 64) { \
                    v = *(const float4*)(Xsrc + ((size_t)(b*256 + (m0)+m))*64 + c4); \
                } else if (CSP == 128) { \
                    v = *(const float4*)(xin + (size_t)b*xbs + (size_t)((m0)+m)*XLD + (c4-64)); \
                } else { \
                    float t0 = (c4-64+0 < XLD) ? xin[(size_t)b*xbs + (size_t)((m0)+m)*XLD + (c4-64)]   : 0.f; \
                    float t1 = (c4-64+1 < XLD) ? xin[(size_t)b*xbs + (size_t)((m0)+m)*XLD + (c4-63)] : 0.f; \
                    v = make_float4(t0, t1, 0.f, 0.f); \
                } \
                v.x *= s; v.y *= s; v.z *= s; v.w *= s; \
                xreg[m] = v; \
            } \
        } \
        areg = *(const float2*)(arow + (m0) + la_m); \
    } while (0)

    #define STOREC(buf) do { \
        if (act) { \
            _Pragma("unroll") \
            for (int m = 0; m < 8; m++) \
                *(float4*)&Xs[(((buf)*8 + b)*8 + m)*CSP + c4] = xreg[m]; \
        } \
        As[(buf)*512 + (la_b*8 + la_m  )*8 + la_k*4 + la_nj] = areg.x; \
        As[(buf)*512 + (la_b*8 + la_m+1)*8 + la_k*4 + la_nj] = areg.y; \
    } while (0)

    LOADC(0); STOREC(0); __syncthreads();
    #pragma unroll 1
    for (int ch = 0; ch < 32; ch++) {
        int buf = ch & 1;
        if (ch < 31) LOADC((ch+1)*8);
        if (act) {
            #pragma unroll
            for (int m = 0; m < 8; m++) {
                float4 xv = *(const float4*)&Xs[((buf*8 + b)*8 + m)*CSP + c4];
                float4 a0 = *(const float4*)&As[buf*512 + (b*8 + m)*8 + 0];
                float4 a1 = *(const float4*)&As[buf*512 + (b*8 + m)*8 + 4];
                acc[0][0][0] += a0.x*xv.x; acc[0][0][1] += a0.x*xv.y; acc[0][0][2] += a0.x*xv.z; acc[0][0][3] += a0.x*xv.w;
                acc[0][1][0] += a0.y*xv.x; acc[0][1][1] += a0.y*xv.y; acc[0][1][2] += a0.y*xv.z; acc[0][1][3] += a0.y*xv.w;
                acc[0][2][0] += a0.z*xv.x; acc[0][2][1] += a0.z*xv.y; acc[0][2][2] += a0.z*xv.z; acc[0][2][3] += a0.z*xv.w;
                acc[0][3][0] += a0.w*xv.x; acc[0][3][1] += a0.w*xv.y; acc[0][3][2] += a0.w*xv.z; acc[0][3][3] += a0.w*xv.w;
                acc[1][0][0] += a1.x*xv.x; acc[1][0][1] += a1.x*xv.y; acc[1][0][2] += a1.x*xv.z; acc[1][0][3] += a1.x*xv.w;
                acc[1][1][0] += a1.y*xv.x; acc[1][1][1] += a1.y*xv.y; acc[1][1][2] += a1.y*xv.z; acc[1][1][3] += a1.y*xv.w;
                acc[1][2][0] += a1.z*xv.x; acc[1][2][1] += a1.z*xv.y; acc[1][2][2] += a1.z*xv.z; acc[1][2][3] += a1.z*xv.w;
                acc[1][3][0] += a1.w*xv.x; acc[1][3][1] += a1.w*xv.y; acc[1][3][2] += a1.w*xv.z; acc[1][3][3] += a1.w*xv.w;
            }
        }
        __syncthreads();
        if (ch < 31) { STOREC((ch+1) & 1); __syncthreads(); }
    }
    #undef LOADC
    #undef STOREC

    // write G (+Ppa for gate state-cols), and gx for gate x-cols
    if (act) {
        #pragma unroll
        for (int k = 0; k < 2; k++)
            #pragma unroll
            for (int nj = 0; nj < 4; nj++) {
                float4 v = make_float4(acc[k][nj][0], acc[k][nj][1], acc[k][nj][2], acc[k][nj][3]);
                int n = n0 + nj;
                if (MODE == 0 && c4 < 64) {
                    float4 p = *(const float4*)(Ppa_t + ((size_t)(b*2+k)*256 + n)*64 + c4);
                    v.x += p.x; v.y += p.y; v.z += p.z; v.w += p.w;
                }
                *(float4*)&G[((b*4 + nj)*2 + k)*CSP + c4] = v;
                if (MODE == 0 && c4 >= 64) {
                    float* gp = gx_out + ((size_t)(b*2+k)*256 + n)*XLD + (c4 - 64);
                    if (CSP == 128) { *(float4*)gp = v; }
                    else {
                        if (c4-64+0 < XLD) gp[0] = v.x;
                        if (c4-64+1 < XLD) gp[1] = v.y;
                    }
                }
            }
    }
    __syncthreads();

    // -------- MLP per node --------
    const int K2 = 2*CSR;
    constexpr int GROUPS = 256 / COUT;
    constexpr int NB2 = 8 / GROUPS;
    int o = tid % COUT;
    int bb0 = tid / COUT;
    #pragma unroll 1
    for (int nj = 0; nj < 4; nj++) {
        int n = n0 + nj;
        for (int idx = tid; idx < 8*K2; idx += 256) {
            int bb = idx / K2, r = idx - bb*K2;
            int k = (r >= CSR) ? 1 : 0;
            int c = r - k*CSR;
            float v;
            if (MODE == 0 || c < 64) v = G[((bb*4 + nj)*2 + k)*CSP + c];
            else v = __ldg(gx_in + ((size_t)(bb*2+k)*256 + n)*XLD + (c - 64));
            In[bb*K2 + r] = v;
        }
        __syncthreads();

        float a2[NB2];
        #pragma unroll
        for (int g = 0; g < NB2; g++) a2[g] = 0.f;
        const float* Wn = W + (size_t)n * K2 * COUT + o;
        int kk = 0;
        #pragma unroll 1
        for (; kk + 8 <= K2; kk += 8) {
            float w[8];
            #pragma unroll
            for (int q = 0; q < 8; q++) w[q] = __ldg(Wn + (size_t)(kk+q)*COUT);
            #pragma unroll
            for (int q = 0; q < 8; q++)
                #pragma unroll
                for (int g = 0; g < NB2; g++)
                    a2[g] += In[(bb0 + g*GROUPS)*K2 + kk + q] * w[q];
        }
        for (; kk < K2; kk++) {
            float w = __ldg(Wn + (size_t)kk*COUT);
            #pragma unroll
            for (int g = 0; g < NB2; g++)
                a2[g] += In[(bb0 + g*GROUPS)*K2 + kk] * w;
        }
        float bv = Bv[n*COUT + o];
        #pragma unroll
        for (int g = 0; g < NB2; g++) {
            int bb = bb0 + g*GROUPS;
            size_t bn = (size_t)bb*256 + n;
            size_t pbn = (size_t)bb*(T_*N_*H_) + (size_t)n*64;
            if (MODE == 0) {
                float val = 1.f / (1.f + __expf(-(a2[g] + bv)));
                if (o < 64) o1[bn*64 + o] = val * (sold[bn*64 + o] + pa_t[pbn + o]);
                else        o2[bn*64 + (o - 64)] = val;
            } else {
                float hc = tanhf(a2[g] + bv);
                float se = sold[bn*64 + o] + pa_t[pbn + o];
                float rr = rbuf_in[bn*64 + o];
                float s  = rr*se + (1.f - rr)*hc;
                o1[bn*64 + o] = s;
                o2[pbn + o]   = s;
                if (hid) hid[bn*64 + o] = s;
            }
        }
        __syncthreads();
    }
}

static float* symaddr(const void* sym) {
    void* p = nullptr;
    cudaGetSymbolAddress(&p, sym);
    return (float*)p;
}

// dynamic smem sizes (bytes)
static constexpr int smem_sz(int CSP, int CSR) {
    return (2*8*8*CSP + 2*512 + 8*4*2*CSP + 8*2*CSR) * 4;
}

extern "C" void kernel_launch(void* const* d_in, const int* in_sizes, int n_in,
                              void* d_out, int out_size) {
    const float* x    = (const float*)d_in[0];
    const float* ist  = (const float*)d_in[1];
    const float* E    = (const float*)d_in[2];
    const float* pa   = (const float*)d_in[3];
    const float* gw0  = (const float*)d_in[4];
    const float* gb0  = (const float*)d_in[5];
    const float* uw0  = (const float*)d_in[6];
    const float* ub0  = (const float*)d_in[7];
    const float* gw1  = (const float*)d_in[8];
    const float* gb1  = (const float*)d_in[9];
    const float* uw1  = (const float*)d_in[10];
    const float* ub1  = (const float*)d_in[11];
    float* out = (float*)d_out;

    float* adj  = symaddr(g_adj);
    float* S    = symaddr(g_S);
    float* invd = symaddr(g_invd);
    float* Wg0  = symaddr(g_Wg0);
    float* Wu0  = symaddr(g_Wu0);
    float* Wg1  = symaddr(g_Wg1);
    float* Wu1  = symaddr(g_Wu1);
    float* Bg0  = symaddr(g_Bg0);
    float* Bu0  = symaddr(g_Bu0);
    float* Bg1  = symaddr(g_Bg1);
    float* Bu1  = symaddr(g_Bu1);
    float* Ppa  = symaddr(g_Ppa);
    float* gx   = symaddr(g_gx);
    float* zs   = symaddr(g_zs);
    float* rbuf = symaddr(g_rbuf);
    float* state= symaddr(g_state);
    float* seq0 = symaddr(g_seq0);

    // raise dynamic smem limits (host attribute set; not a stream op)
    cudaFuncSetAttribute(fused_k<68,66,128,0>,  cudaFuncAttributeMaxDynamicSharedMemorySize, smem_sz(68,66));
    cudaFuncSetAttribute(fused_k<64,66,64,1>,   cudaFuncAttributeMaxDynamicSharedMemorySize, smem_sz(64,66));
    cudaFuncSetAttribute(fused_k<128,128,128,0>,cudaFuncAttributeMaxDynamicSharedMemorySize, smem_sz(128,128));
    cudaFuncSetAttribute(fused_k<64,128,64,1>,  cudaFuncAttributeMaxDynamicSharedMemorySize, smem_sz(64,128));

    const size_t ZY = (size_t)2*256*64;
    float* hid0 = out + (size_t)B_*T_*N_*H_;
    float* hid1 = hid0 + (size_t)B_*N_*H_;

    // -------- precompute --------
    adj_k<<<256, 256>>>(E, adj);
    wexpand_all<<<dim3(256, 4), 128>>>(E, gw0, uw0, gw1, uw1, Wg0, Wu0, Wg1, Wu1);
    bexpand_all<<<dim3(256, 4), 128>>>(E, gb0, ub0, gb1, ub1, Bg0, Bu0, Bg1, Bu1);
    sker_k<<<dim3(TB_, 4), 256>>>(pa, S);
    invd_k<<<TB_, 256>>>(S, invd);
    gemm_k<0,0><<<dim3(4, 4, TB_), 256>>>(adj, 0, S, 256, 2*NN_, nullptr, 0,
                                          S + NN_, 256, 2*NN_);
    gemm_k<0,1><<<dim3(1, 8, TB_), 256>>>(S, 2*NN_, pa, 64, 0, invd, N_,
                                          Ppa, 64, ZY);

    // -------- recurrent loops (2 fused kernels per step) --------
    for (int layer = 0; layer < 2; layer++) {
        const float* Wg = layer ? Wg1 : Wg0;
        const float* Bg = layer ? Bg1 : Bg0;
        const float* Wu = layer ? Wu1 : Wu0;
        const float* Bu = layer ? Bu1 : Bu0;
        float* seqout = layer ? out : seq0;
        float* hid    = layer ? hid1 : hid0;
        size_t xbs    = layer ? (size_t)T_*N_*64 : (size_t)T_*N_*2;

        for (int t = 0; t < T_; t++) {
            const float* sp  = t ? state : (ist + (size_t)layer*B_*N_*H_);
            const float* Sb  = S + (size_t)t*8*2*NND;
            const float* ivt = invd + (size_t)t*8*N_;
            const float* pat = pa + (size_t)t*N_*H_;
            const float* Ppt = Ppa + (size_t)t*8*ZY;
            const float* xin = layer ? (seq0 + (size_t)t*N_*64) : (x + (size_t)t*N_*2);
            float* seqt = seqout + (size_t)t*N_*H_;
            float* hidt = (t == T_-1) ? hid : nullptr;

            if (layer == 0) {
                fused_k<68,66,128,0><<<64, 256, smem_sz(68,66)>>>(
                    Sb, ivt, sp, xin, xbs, Ppt, Wg, Bg, sp, pat,
                    nullptr, nullptr, gx, zs, rbuf, nullptr);
                fused_k<64,66,64,1><<<64, 256, smem_sz(64,66)>>>(
                    Sb, ivt, zs, nullptr, 0, nullptr, Wu, Bu, sp, pat,
                    rbuf, gx, nullptr, state, seqt, hidt);
            } else {
                fused_k<128,128,128,0><<<64, 256, smem_sz(128,128)>>>(
                    Sb, ivt, sp, xin, xbs, Ppt, Wg, Bg, sp, pat,
                    nullptr, nullptr, gx, zs, rbuf, nullptr);
                fused_k<64,128,64,1><<<64, 256, smem_sz(64,128)>>>(
                    Sb, ivt, zs, nullptr, 0, nullptr, Wu, Bu, sp, pat,
                    rbuf, gx, nullptr, state, seqt, hidt);
            }
        }
    }
}

// round 14
// speedup vs baseline: 2.4963x; 2.4963x over previous
#include <cuda_runtime.h>
#include <cuda_bf16.h>
#include <math.h>

#define B_  8
#define T_  12
#define N_  256
#define H_  64
#define E_  16
#define TB_ (T_*B_)
static const size_t NN_ = (size_t)N_*N_;

// ---------------- static device scratch ----------------
__device__ float g_adj[N_*N_];
__device__ float g_S[TB_*2*N_*N_];          // (tb, slot{S, adj@S}, N, N)
__device__ float g_invd[TB_*N_];
__device__ float g_Wg0[256*132*128];
__device__ float g_Wu0[256*132*64];
__device__ float g_Wg1[256*256*128];
__device__ float g_Wu1[256*256*64];
__device__ float g_Bg0[256*128];
__device__ float g_Bu0[256*64];
__device__ float g_Bg1[256*128];
__device__ float g_Bu1[256*64];
__device__ float g_Ppa[TB_*2*256*64];       // sup @ (invd*pa_t)
__device__ float g_Px0[TB_*2*256*2];        // sup @ (invd*x_t) layer0
__device__ float g_Px1[TB_*2*256*64];       // sup @ (invd*seq0_t) layer1
__device__ float g_ys[2*8*2*256*64];        // 2 K-split partials, gate GCN
__device__ float g_us[2*8*2*256*64];        // 2 K-split partials, update GCN
__device__ float g_zs[8*256*64];
__device__ float g_rbuf[8*256*64];
__device__ float g_state[8*256*64];
__device__ float g_seq0[8*12*256*64];

#define PART_ ((size_t)8*2*256*64)          // per-partial stride in ys/us

// ---------------- adj = softmax(relu(E E^T), axis=1) ----------------
__global__ __launch_bounds__(256) void adj_k(const float* __restrict__ E, float* __restrict__ adj) {
    __shared__ float sE[N_*E_];
    __shared__ float red[N_];
    int n = blockIdx.x, m = threadIdx.x;
    for (int i = m; i < N_*E_; i += 256) sE[i] = E[i];
    __syncthreads();
    float dot = 0.f;
    #pragma unroll
    for (int e = 0; e < E_; e++) dot += sE[n*E_+e] * sE[m*E_+e];
    float sc = fmaxf(dot, 0.f);
    red[m] = sc; __syncthreads();
    for (int s = 128; s > 0; s >>= 1) { if (m < s) red[m] = fmaxf(red[m], red[m+s]); __syncthreads(); }
    float mx = red[0]; __syncthreads();
    float ex = __expf(sc - mx);
    red[m] = ex; __syncthreads();
    for (int s = 128; s > 0; s >>= 1) { if (m < s) red[m] += red[m+s]; __syncthreads(); }
    adj[n*N_+m] = ex / red[0];
}

// ---------------- fused per-node weight expansion (all 4 pools) ----------------
__global__ __launch_bounds__(128) void wexpand_all(
    const float* __restrict__ E,
    const float* __restrict__ p0, const float* __restrict__ p1,
    const float* __restrict__ p2, const float* __restrict__ p3,
    float* __restrict__ w0, float* __restrict__ w1,
    float* __restrict__ w2, float* __restrict__ w3)
{
    __shared__ float sE[256][16];
    int tid = threadIdx.x;
    for (int i = tid; i < 256*16; i += 128) sE[i>>4][i&15] = E[i];
    __syncthreads();
    int which = blockIdx.y;
    int Cin  = (which < 2) ? 66 : 128;
    int Cout = (which & 1) ? 64 : 128;
    int Din  = (which < 2) ? 2 : 64;
    const float* pool = which==0?p0:which==1?p1:which==2?p2:p3;
    float* Wp         = which==0?w0:which==1?w1:which==2?w2:w3;
    int r = blockIdx.x;
    if (r >= 2*Cin) return;
    int o = tid;
    if (o >= Cout) return;
    int k = (r >= Cin) ? 1 : 0;
    int c = r - k*Cin;
    int i = (c < 64) ? (Din + c) : (c - 64);
    float pe[16];
    #pragma unroll
    for (int e = 0; e < 16; e++)
        pe[e] = pool[(((size_t)e*2 + k)*Cin + i)*Cout + o];
    size_t K2C = (size_t)2*Cin*Cout;
    float* outp = Wp + (size_t)r*Cout + o;
    for (int n = 0; n < 256; n++) {
        float4 a  = *(const float4*)&sE[n][0];
        float4 b  = *(const float4*)&sE[n][4];
        float4 cc = *(const float4*)&sE[n][8];
        float4 d  = *(const float4*)&sE[n][12];
        float acc = a.x*pe[0]+a.y*pe[1]+a.z*pe[2]+a.w*pe[3]
                  + b.x*pe[4]+b.y*pe[5]+b.z*pe[6]+b.w*pe[7]
                  + cc.x*pe[8]+cc.y*pe[9]+cc.z*pe[10]+cc.w*pe[11]
                  + d.x*pe[12]+d.y*pe[13]+d.z*pe[14]+d.w*pe[15];
        outp[(size_t)n*K2C] = acc;
    }
}

__global__ void bexpand_all(const float* __restrict__ E,
    const float* __restrict__ b0, const float* __restrict__ b1,
    const float* __restrict__ b2, const float* __restrict__ b3,
    float* __restrict__ o0, float* __restrict__ o1,
    float* __restrict__ o2, float* __restrict__ o3)
{
    int which = blockIdx.y;
    int Cout = (which & 1) ? 64 : 128;
    const float* bp = which==0?b0:which==1?b1:which==2?b2:b3;
    float* outp     = which==0?o0:which==1?o1:which==2?o2:o3;
    int n = blockIdx.x, o = threadIdx.x;
    if (o >= Cout) return;
    float acc = 0.f;
    #pragma unroll
    for (int e = 0; e < 16; e++) acc += E[n*16+e]*bp[e*Cout+o];
    outp[n*Cout+o] = acc;
}

// ---------------- S[tb,i,j] = exp(-L1(pa[b,t,i], pa[b,t,j])) ----------------
__global__ __launch_bounds__(256) void sker_k(const float* __restrict__ pa, float* __restrict__ S) {
    __shared__ float pi[64][68];
    __shared__ float pj[64][68];
    int tb = blockIdx.x;
    int t = tb >> 3, b = tb & 7;
    int i0 = blockIdx.y * 64;
    int tid = threadIdx.x;
    const float* pab = pa + (((size_t)b*T_ + t)*N_) * H_;
    for (int idx = tid; idx < 64*64; idx += 256) {
        int r = idx >> 6, h = idx & 63;
        pi[r][h] = pab[(size_t)(i0+r)*H_ + h];
    }
    float* Sb = S + (size_t)tb * 2 * NN_;
    int il = (tid >> 4) << 2;
    int jl = (tid & 15) << 2;
    for (int j0 = 0; j0 < N_; j0 += 64) {
        __syncthreads();
        for (int idx = tid; idx < 64*64; idx += 256) {
            int r = idx >> 6, h = idx & 63;
            pj[r][h] = pab[(size_t)(j0+r)*H_ + h];
        }
        __syncthreads();
        float d[4][4] = {};
        #pragma unroll
        for (int h = 0; h < 64; h += 4) {
            float4 a[4], c[4];
            #pragma unroll
            for (int q = 0; q < 4; q++) a[q] = *(const float4*)&pi[il+q][h];
            #pragma unroll
            for (int q = 0; q < 4; q++) c[q] = *(const float4*)&pj[jl+q][h];
            #pragma unroll
            for (int ii = 0; ii < 4; ii++)
                #pragma unroll
                for (int jj = 0; jj < 4; jj++)
                    d[ii][jj] += fabsf(a[ii].x-c[jj].x) + fabsf(a[ii].y-c[jj].y)
                               + fabsf(a[ii].z-c[jj].z) + fabsf(a[ii].w-c[jj].w);
        }
        #pragma unroll
        for (int ii = 0; ii < 4; ii++) {
            float4 v = make_float4(__expf(-d[ii][0]), __expf(-d[ii][1]),
                                   __expf(-d[ii][2]), __expf(-d[ii][3]));
            *(float4*)&Sb[(size_t)(i0+il+ii)*N_ + j0 + jl] = v;
        }
    }
}

__global__ void invd_k(const float* __restrict__ S, float* __restrict__ invd) {
    int tb = blockIdx.x, j = threadIdx.x;
    const float* Sb = S + (size_t)tb * 2 * NN_;
    float s = 0.f;
    #pragma unroll 8
    for (int i = 0; i < N_; i++) s += Sb[(size_t)i*N_ + j];
    invd[tb*N_ + j] = 1.f / s;
}

// ---------------- precompute SGEMM (R11 proven, double-buffered) ----------------
template<int KSPLIT, int XMAP>
__global__ __launch_bounds__(256) void gemm_k(
    const float* __restrict__ A, size_t aStride,
    const float* __restrict__ X, int ldx, size_t xStride,
    const float* __restrict__ invd, int ivStride,
    float* __restrict__ Y, int ldy, size_t yStride)
{
    __shared__ float As[2][16][68];
    __shared__ float Xs[2][16][64];
    const int KL = KSPLIT ? 128 : 256;
    int z = blockIdx.z;
    int b    = KSPLIT ? (z & 7) : z;
    int koff = KSPLIT ? ((z >> 3) * 128) : 0;
    const float* Az = A + (size_t)b * aStride + koff;
    const float* Xz;
    if (XMAP) {
        int t = z >> 3, bb = z & 7;
        Xz = X + ((size_t)(bb*T_ + t)) * N_ * ldx;
    } else {
        Xz = X + (size_t)b * xStride + (size_t)koff * ldx;
    }
    float* Yz = Y + (size_t)z * yStride;
    const float* iv = invd ? (invd + (size_t)(XMAP ? z : b) * ivStride + koff) : nullptr;
    int m0 = blockIdx.y * 64, c0 = blockIdx.x * 64;
    int tid = threadIdx.x;
    int tx = tid & 15, ty = tid >> 4;
    int a_m = tid >> 2, a_k = (tid & 3) * 4;
    int x_k = tid >> 4, x_c = (tid & 15) * 4;
    float acc[4][4] = {};

    float4 av = *(const float4*)&Az[(size_t)(m0 + a_m)*256 + a_k];
    float4 xv = *(const float4*)&Xz[(size_t)(x_k)*ldx + c0 + x_c];
    if (iv) { float s = iv[x_k]; xv.x *= s; xv.y *= s; xv.z *= s; xv.w *= s; }

    int cur = 0;
    for (int k0 = 0; k0 < KL; k0 += 16) {
        As[cur][a_k+0][a_m] = av.x; As[cur][a_k+1][a_m] = av.y;
        As[cur][a_k+2][a_m] = av.z; As[cur][a_k+3][a_m] = av.w;
        *(float4*)&Xs[cur][x_k][x_c] = xv;
        __syncthreads();
        if (k0 + 16 < KL) {
            av = *(const float4*)&Az[(size_t)(m0 + a_m)*256 + k0 + 16 + a_k];
            xv = *(const float4*)&Xz[(size_t)(k0 + 16 + x_k)*ldx + c0 + x_c];
            if (iv) { float s = iv[k0 + 16 + x_k]; xv.x *= s; xv.y *= s; xv.z *= s; xv.w *= s; }
        }
        #pragma unroll
        for (int kk = 0; kk < 16; kk++) {
            float4 a4 = *(const float4*)&As[cur][kk][ty*4];
            float4 x4 = *(const float4*)&Xs[cur][kk][tx*4];
            acc[0][0] += a4.x*x4.x; acc[0][1] += a4.x*x4.y; acc[0][2] += a4.x*x4.z; acc[0][3] += a4.x*x4.w;
            acc[1][0] += a4.y*x4.x; acc[1][1] += a4.y*x4.y; acc[1][2] += a4.y*x4.z; acc[1][3] += a4.y*x4.w;
            acc[2][0] += a4.z*x4.x; acc[2][1] += a4.z*x4.y; acc[2][2] += a4.z*x4.z; acc[2][3] += a4.z*x4.w;
            acc[3][0] += a4.w*x4.x; acc[3][1] += a4.w*x4.y; acc[3][2] += a4.w*x4.z; acc[3][3] += a4.w*x4.w;
        }
        cur ^= 1;
    }
    #pragma unroll
    for (int i = 0; i < 4; i++) {
        float4 v = make_float4(acc[i][0], acc[i][1], acc[i][2], acc[i][3]);
        *(float4*)&Yz[(size_t)(m0 + ty*4 + i)*ldy + c0 + tx*4] = v;
    }
}

// ---------------- step SGEMM: 32-row M-tiles (256 blocks; K-split 2) ----------------
// Y[z=kz*8+b] (512x64) partial over K range [kz*128, kz*128+128)
__global__ __launch_bounds__(256) void gemm32_k(
    const float* __restrict__ A, size_t aStride,
    const float* __restrict__ X, size_t xStride,
    const float* __restrict__ invd, int ivStride,
    float* __restrict__ Y, size_t yStride)
{
    __shared__ float As[2][16][34];
    __shared__ float Xs[2][16][64];
    int z = blockIdx.z;
    int b = z & 7;
    int koff = (z >> 3) * 128;
    const float* Az = A + (size_t)b * aStride + koff;
    const float* Xz = X + (size_t)b * xStride + (size_t)koff * 64;
    float* Yz = Y + (size_t)z * yStride;
    const float* iv = invd + (size_t)b * ivStride + koff;
    int m0 = blockIdx.y * 32;
    int tid = threadIdx.x;
    int tx = tid & 15, ty = tid >> 4;
    int a_m = tid >> 3, a_k = (tid & 7) * 2;
    int x_k = tid >> 4, x_c = (tid & 15) * 4;
    float acc[2][4] = {};

    float2 av = *(const float2*)&Az[(size_t)(m0 + a_m)*256 + a_k];
    float4 xv = *(const float4*)&Xz[(size_t)(x_k)*64 + x_c];
    { float s = iv[x_k]; xv.x *= s; xv.y *= s; xv.z *= s; xv.w *= s; }

    int cur = 0;
    for (int k0 = 0; k0 < 128; k0 += 16) {
        As[cur][a_k+0][a_m] = av.x;
        As[cur][a_k+1][a_m] = av.y;
        *(float4*)&Xs[cur][x_k][x_c] = xv;
        __syncthreads();
        if (k0 + 16 < 128) {
            av = *(const float2*)&Az[(size_t)(m0 + a_m)*256 + k0 + 16 + a_k];
            xv = *(const float4*)&Xz[(size_t)(k0 + 16 + x_k)*64 + x_c];
            float s = iv[k0 + 16 + x_k]; xv.x *= s; xv.y *= s; xv.z *= s; xv.w *= s;
        }
        #pragma unroll
        for (int kk = 0; kk < 16; kk++) {
            float a0 = As[cur][kk][ty*2];
            float a1 = As[cur][kk][ty*2+1];
            float4 x4 = *(const float4*)&Xs[cur][kk][tx*4];
            acc[0][0] += a0*x4.x; acc[0][1] += a0*x4.y; acc[0][2] += a0*x4.z; acc[0][3] += a0*x4.w;
            acc[1][0] += a1*x4.x; acc[1][1] += a1*x4.y; acc[1][2] += a1*x4.z; acc[1][3] += a1*x4.w;
        }
        cur ^= 1;
    }
    #pragma unroll
    for (int i = 0; i < 2; i++) {
        float4 v = make_float4(acc[i][0], acc[i][1], acc[i][2], acc[i][3]);
        *(float4*)&Yz[(size_t)(m0 + ty*2 + i)*64 + tx*4] = v;
    }
}

// ---------------- layer0 x-part: Px0[tb, row, 0..1] = sup[row,:] @ (invd*x_t) ----------------
__global__ __launch_bounds__(256) void px0_k(const float* __restrict__ S,
    const float* __restrict__ x, const float* __restrict__ invd,
    float* __restrict__ Px0)
{
    __shared__ float xs[256][2];
    int z = blockIdx.x;
    int t = z >> 3, b = z & 7;
    int tid = threadIdx.x;
    const float* xb = x + ((size_t)(b*T_ + t))*N_*2;
    {
        int m = tid;
        float s = invd[z*N_ + m];
        xs[m][0] = xb[m*2+0]*s;
        xs[m][1] = xb[m*2+1]*s;
    }
    __syncthreads();
    int w = tid >> 5, lane = tid & 31;
    int row = blockIdx.y * 8 + w;
    const float* Ar = S + (size_t)z*2*NN_ + (size_t)row*256;
    float a0 = 0.f, a1 = 0.f;
    #pragma unroll
    for (int m = lane; m < 256; m += 32) {
        float a = Ar[m];
        a0 += a*xs[m][0];
        a1 += a*xs[m][1];
    }
    #pragma unroll
    for (int off = 16; off; off >>= 1) {
        a0 += __shfl_down_sync(0xffffffff, a0, off);
        a1 += __shfl_down_sync(0xffffffff, a1, off);
    }
    if (!lane) {
        Px0[(size_t)z*1024 + row*2 + 0] = a0;
        Px0[(size_t)z*1024 + row*2 + 1] = a1;
    }
}

// ---------------- per-node batched MLP with fused GRU epilogues ----------------
// o-split: grid 512 = 256 nodes x 2 halves; OW outputs per block.
// o-major + 8-wide explicit weight prefetch (R11 proven inner loop).
// MODE 0 (gate): sigmoid; o<64: zs = z*(state+pa); o>=64: rbuf = r
// MODE 1 (upd):  tanh -> hc; s = r*(state+pa)+(1-r)*hc -> state, seq
template<int OW, int COUT, int NB, int MODE>
__global__ __launch_bounds__(256) void mlp_k(
    const float* __restrict__ ys, size_t ysPart,
    const float* __restrict__ Ppa_t,
    const float* __restrict__ Px_t, int dinCols, int CS,
    const float* __restrict__ W, const float* __restrict__ bias,
    const float* __restrict__ state, const float* __restrict__ pa_t,
    const float* __restrict__ rbuf,
    float* __restrict__ o1, float* __restrict__ o2)
{
    __shared__ float Xs[8*256];
    int bx = blockIdx.x;
    int n = bx & 255, half = bx >> 8;
    int tid = threadIdx.x;
    int K2 = 2*CS;
    for (int idx = tid; idx < 8*K2; idx += 256) {
        int b = idx / K2, r = idx - b*K2;
        int k = (r >= CS) ? 1 : 0;
        int c = r - k*CS;
        float v;
        size_t base = ((size_t)(b*2 + k)*256 + n)*64;
        if (c < 64) {
            v = ys[base + c] + ys[ysPart + base + c];
            if (MODE == 0) v += Ppa_t[base + c];
        } else {
            v = Px_t[((size_t)(b*2 + k)*256 + n)*dinCols + (c - 64)];
        }
        Xs[b*K2 + r] = v;
    }
    __syncthreads();
    constexpr int GROUPS = 256 / OW;
    int o = half*OW + (tid % OW);
    int bb0 = tid / OW;
    float acc[NB];
    #pragma unroll
    for (int g = 0; g < NB; g++) acc[g] = 0.f;
    const float* Wn = W + (size_t)n * K2 * COUT + o;

    int kk = 0;
    #pragma unroll 1
    for (; kk + 8 <= K2; kk += 8) {
        float w[8];
        #pragma unroll
        for (int q = 0; q < 8; q++)
            w[q] = __ldg(Wn + (size_t)(kk + q)*COUT);
        #pragma unroll
        for (int q = 0; q < 8; q++) {
            #pragma unroll
            for (int g = 0; g < NB; g++)
                acc[g] += Xs[(bb0 + g*GROUPS)*K2 + kk + q] * w[q];
        }
    }
    for (; kk < K2; kk++) {
        float w = __ldg(Wn + (size_t)kk*COUT);
        #pragma unroll
        for (int g = 0; g < NB; g++)
            acc[g] += Xs[(bb0 + g*GROUPS)*K2 + kk] * w;
    }

    float bv = bias[n*COUT + o];
    #pragma unroll
    for (int g = 0; g < NB; g++) {
        int b = bb0 + g*GROUPS;
        size_t bn = (size_t)b*256 + n;
        size_t pbn = (size_t)b*(T_*N_*H_) + (size_t)n*64;
        if (MODE == 0) {
            float val = 1.f / (1.f + __expf(-(acc[g] + bv)));
            if (o < 64) o1[bn*64 + o] = val * (state[bn*64 + o] + pa_t[pbn + o]);
            else        o2[bn*64 + (o - 64)] = val;
        } else {
            float hc = tanhf(acc[g] + bv);
            float se = state[bn*64 + o] + pa_t[pbn + o];
            float rr = rbuf[bn*64 + o];
            float s  = rr*se + (1.f - rr)*hc;
            o1[bn*64 + o] = s;
            o2[pbn + o]   = s;
        }
    }
}

static float* symaddr(const void* sym) {
    void* p = nullptr;
    cudaGetSymbolAddress(&p, sym);
    return (float*)p;
}

extern "C" void kernel_launch(void* const* d_in, const int* in_sizes, int n_in,
                              void* d_out, int out_size) {
    const float* x    = (const float*)d_in[0];
    const float* ist  = (const float*)d_in[1];
    const float* E    = (const float*)d_in[2];
    const float* pa   = (const float*)d_in[3];
    const float* gw0  = (const float*)d_in[4];
    const float* gb0  = (const float*)d_in[5];
    const float* uw0  = (const float*)d_in[6];
    const float* ub0  = (const float*)d_in[7];
    const float* gw1  = (const float*)d_in[8];
    const float* gb1  = (const float*)d_in[9];
    const float* uw1  = (const float*)d_in[10];
    const float* ub1  = (const float*)d_in[11];
    float* out = (float*)d_out;

    float* adj  = symaddr(g_adj);
    float* S    = symaddr(g_S);
    float* invd = symaddr(g_invd);
    float* Wg0  = symaddr(g_Wg0);
    float* Wu0  = symaddr(g_Wu0);
    float* Wg1  = symaddr(g_Wg1);
    float* Wu1  = symaddr(g_Wu1);
    float* Bg0  = symaddr(g_Bg0);
    float* Bu0  = symaddr(g_Bu0);
    float* Bg1  = symaddr(g_Bg1);
    float* Bu1  = symaddr(g_Bu1);
    float* Ppa  = symaddr(g_Ppa);
    float* Px0  = symaddr(g_Px0);
    float* Px1  = symaddr(g_Px1);
    float* ys   = symaddr(g_ys);
    float* us   = symaddr(g_us);
    float* zs   = symaddr(g_zs);
    float* rbuf = symaddr(g_rbuf);
    float* state= symaddr(g_state);
    float* seq0 = symaddr(g_seq0);

    const size_t ZY = (size_t)2*256*64;        // 32768: per-z GEMM output

    // -------- precompute --------
    adj_k<<<256, 256>>>(E, adj);
    wexpand_all<<<dim3(256, 4), 128>>>(E, gw0, uw0, gw1, uw1, Wg0, Wu0, Wg1, Wu1);
    bexpand_all<<<dim3(256, 4), 128>>>(E, gb0, ub0, gb1, ub1, Bg0, Bu0, Bg1, Bu1);
    sker_k<<<dim3(TB_, 4), 256>>>(pa, S);
    invd_k<<<TB_, 256>>>(S, invd);
    // A2[tb] = adj @ S[tb]  -> slot 1
    gemm_k<0,0><<<dim3(4, 4, TB_), 256>>>(adj, 0, S, 256, 2*NN_, nullptr, 0,
                                          S + NN_, 256, 2*NN_);
    // Ppa[tb] = [S;A2] @ (invd * pa_t)
    gemm_k<0,1><<<dim3(1, 8, TB_), 256>>>(S, 2*NN_, pa, 64, 0, invd, N_,
                                          Ppa, 64, ZY);
    // Px0[tb] = [S;A2] @ (invd * x_t)
    px0_k<<<dim3(TB_, 64), 256>>>(S, x, invd, Px0);

    // -------- recurrent loops --------
    for (int layer = 0; layer < 2; layer++) {
        int CS      = layer ? 128 : 66;
        int dinCols = layer ? 64 : 2;
        const float* Wg = layer ? Wg1 : Wg0;
        const float* Bg = layer ? Bg1 : Bg0;
        const float* Wu = layer ? Wu1 : Wu0;
        const float* Bu = layer ? Bu1 : Bu0;
        const float* Px = layer ? Px1 : Px0;
        float* seqout = layer ? out : seq0;

        if (layer) {
            // Px1[tb] = [S;A2] @ (invd * seq0_t)  (parallel over all t)
            gemm_k<0,1><<<dim3(1, 8, TB_), 256>>>(S, 2*NN_, seq0, 64, 0, invd, N_,
                                                  Px1, 64, ZY);
        }

        for (int t = 0; t < T_; t++) {
            const float* sp = t ? state : (ist + (size_t)layer*B_*N_*H_);
            const float* At = S + (size_t)t*8*2*NN_;
            const float* iv = invd + (size_t)t*8*N_;
            const float* pat = pa + (size_t)t*N_*H_;
            const float* Ppt = Ppa + (size_t)t*8*ZY;
            const float* Pxt = Px + (size_t)t*8*512*dinCols;

            // gate GCN on state columns (32-row tiles, K-split 2 -> 256 blocks)
            gemm32_k<<<dim3(1, 16, 16), 256>>>(At, 2*NN_, sp, (size_t)N_*64,
                                               iv, N_, ys, ZY);
            if (layer)
                mlp_k<64,128,2,0><<<512, 256>>>(ys, PART_, Ppt, Pxt, 64, 128,
                                                Wg, Bg, sp, pat, nullptr, zs, rbuf);
            else
                mlp_k<64,128,2,0><<<512, 256>>>(ys, PART_, Ppt, Pxt, 2, 66,
                                                Wg, Bg, sp, pat, nullptr, zs, rbuf);
            // update GCN on zs
            gemm32_k<<<dim3(1, 16, 16), 256>>>(At, 2*NN_, zs, (size_t)N_*64,
                                               iv, N_, us, ZY);
            if (layer)
                mlp_k<32,64,1,1><<<512, 256>>>(us, PART_, nullptr, Pxt, 64, 128,
                                               Wu, Bu, sp, pat, rbuf,
                                               state, seqout + (size_t)t*N_*H_);
            else
                mlp_k<32,64,1,1><<<512, 256>>>(us, PART_, nullptr, Pxt, 2, 66,
                                               Wu, Bu, sp, pat, rbuf,
                                               state, seqout + (size_t)t*N_*H_);
        }
        cudaMemcpyAsync(out + (size_t)B_*T_*N_*H_ + (size_t)layer*B_*N_*H_,
                        state, (size_t)B_*N_*H_*sizeof(float),
                        cudaMemcpyDeviceToDevice);
    }
}

// round 15
// speedup vs baseline: 2.6680x; 1.0688x over previous
#include <cuda_runtime.h>
#include <cuda_bf16.h>
#include <math.h>

#define B_  8
#define T_  12
#define N_  256
#define H_  64
#define E_  16
#define TB_ (T_*B_)
#define NND ((size_t)65536)
#define NBLK 256
static const size_t NN_ = (size_t)N_*N_;

// ---------------- static device scratch ----------------
__device__ float g_adj[N_*N_];
__device__ float g_S[TB_*2*N_*N_];          // (tb, slot{S, adj@S}, N, N)
__device__ float g_invd[TB_*N_];
__device__ float g_Wg0[256*132*128];
__device__ float g_Wu0[256*132*64];
__device__ float g_Wg1[256*256*128];
__device__ float g_Wu1[256*256*64];
__device__ float g_Bg0[256*128];
__device__ float g_Bu0[256*64];
__device__ float g_Bg1[256*128];
__device__ float g_Bu1[256*64];
__device__ float g_Ppa[TB_*2*256*64];       // sup @ (invd*pa_t)
__device__ float g_Px0[TB_*2*256*2];        // sup @ (invd*x_t) layer0
__device__ float g_Px1[TB_*2*256*64];       // sup @ (invd*seq0_t) layer1
__device__ float g_ys[2*8*2*256*64];        // 2 K-split partials, gate GCN
__device__ float g_us[2*8*2*256*64];        // 2 K-split partials, update GCN
__device__ float g_zs[8*256*64];
__device__ float g_rbuf[8*256*64];
__device__ float g_state[8*256*64];
__device__ float g_seq0[8*12*256*64];
__device__ unsigned g_count = 0;
__device__ unsigned g_sense = 0;

#define PART_ ((size_t)8*2*256*64)          // per-partial stride in ys/us

// ---------------- adj = softmax(relu(E E^T), axis=1) ----------------
__global__ __launch_bounds__(256) void adj_k(const float* __restrict__ E, float* __restrict__ adj) {
    __shared__ float sE[N_*E_];
    __shared__ float red[N_];
    int n = blockIdx.x, m = threadIdx.x;
    for (int i = m; i < N_*E_; i += 256) sE[i] = E[i];
    __syncthreads();
    float dot = 0.f;
    #pragma unroll
    for (int e = 0; e < E_; e++) dot += sE[n*E_+e] * sE[m*E_+e];
    float sc = fmaxf(dot, 0.f);
    red[m] = sc; __syncthreads();
    for (int s = 128; s > 0; s >>= 1) { if (m < s) red[m] = fmaxf(red[m], red[m+s]); __syncthreads(); }
    float mx = red[0]; __syncthreads();
    float ex = __expf(sc - mx);
    red[m] = ex; __syncthreads();
    for (int s = 128; s > 0; s >>= 1) { if (m < s) red[m] += red[m+s]; __syncthreads(); }
    adj[n*N_+m] = ex / red[0];
}

// ---------------- fused per-node weight expansion (all 4 pools) ----------------
__global__ __launch_bounds__(128) void wexpand_all(
    const float* __restrict__ E,
    const float* __restrict__ p0, const float* __restrict__ p1,
    const float* __restrict__ p2, const float* __restrict__ p3,
    float* __restrict__ w0, float* __restrict__ w1,
    float* __restrict__ w2, float* __restrict__ w3)
{
    __shared__ float sE[256][16];
    int tid = threadIdx.x;
    for (int i = tid; i < 256*16; i += 128) sE[i>>4][i&15] = E[i];
    __syncthreads();
    int which = blockIdx.y;
    int Cin  = (which < 2) ? 66 : 128;
    int Cout = (which & 1) ? 64 : 128;
    int Din  = (which < 2) ? 2 : 64;
    const float* pool = which==0?p0:which==1?p1:which==2?p2:p3;
    float* Wp         = which==0?w0:which==1?w1:which==2?w2:w3;
    int r = blockIdx.x;
    if (r >= 2*Cin) return;
    int o = tid;
    if (o >= Cout) return;
    int k = (r >= Cin) ? 1 : 0;
    int c = r - k*Cin;
    int i = (c < 64) ? (Din + c) : (c - 64);
    float pe[16];
    #pragma unroll
    for (int e = 0; e < 16; e++)
        pe[e] = pool[(((size_t)e*2 + k)*Cin + i)*Cout + o];
    size_t K2C = (size_t)2*Cin*Cout;
    float* outp = Wp + (size_t)r*Cout + o;
    for (int n = 0; n < 256; n++) {
        float4 a  = *(const float4*)&sE[n][0];
        float4 b  = *(const float4*)&sE[n][4];
        float4 cc = *(const float4*)&sE[n][8];
        float4 d  = *(const float4*)&sE[n][12];
        float acc = a.x*pe[0]+a.y*pe[1]+a.z*pe[2]+a.w*pe[3]
                  + b.x*pe[4]+b.y*pe[5]+b.z*pe[6]+b.w*pe[7]
                  + cc.x*pe[8]+cc.y*pe[9]+cc.z*pe[10]+cc.w*pe[11]
                  + d.x*pe[12]+d.y*pe[13]+d.z*pe[14]+d.w*pe[15];
        outp[(size_t)n*K2C] = acc;
    }
}

__global__ void bexpand_all(const float* __restrict__ E,
    const float* __restrict__ b0, const float* __restrict__ b1,
    const float* __restrict__ b2, const float* __restrict__ b3,
    float* __restrict__ o0, float* __restrict__ o1,
    float* __restrict__ o2, float* __restrict__ o3)
{
    int which = blockIdx.y;
    int Cout = (which & 1) ? 64 : 128;
    const float* bp = which==0?b0:which==1?b1:which==2?b2:b3;
    float* outp     = which==0?o0:which==1?o1:which==2?o2:o3;
    int n = blockIdx.x, o = threadIdx.x;
    if (o >= Cout) return;
    float acc = 0.f;
    #pragma unroll
    for (int e = 0; e < 16; e++) acc += E[n*16+e]*bp[e*Cout+o];
    outp[n*Cout+o] = acc;
}

// ---------------- S[tb,i,j] = exp(-L1(pa[b,t,i], pa[b,t,j])) ----------------
__global__ __launch_bounds__(256) void sker_k(const float* __restrict__ pa, float* __restrict__ S) {
    __shared__ float pi[64][68];
    __shared__ float pj[64][68];
    int tb = blockIdx.x;
    int t = tb >> 3, b = tb & 7;
    int i0 = blockIdx.y * 64;
    int tid = threadIdx.x;
    const float* pab = pa + (((size_t)b*T_ + t)*N_) * H_;
    for (int idx = tid; idx < 64*64; idx += 256) {
        int r = idx >> 6, h = idx & 63;
        pi[r][h] = pab[(size_t)(i0+r)*H_ + h];
    }
    float* Sb = S + (size_t)tb * 2 * NN_;
    int il = (tid >> 4) << 2;
    int jl = (tid & 15) << 2;
    for (int j0 = 0; j0 < N_; j0 += 64) {
        __syncthreads();
        for (int idx = tid; idx < 64*64; idx += 256) {
            int r = idx >> 6, h = idx & 63;
            pj[r][h] = pab[(size_t)(j0+r)*H_ + h];
        }
        __syncthreads();
        float d[4][4] = {};
        #pragma unroll
        for (int h = 0; h < 64; h += 4) {
            float4 a[4], c[4];
            #pragma unroll
            for (int q = 0; q < 4; q++) a[q] = *(const float4*)&pi[il+q][h];
            #pragma unroll
            for (int q = 0; q < 4; q++) c[q] = *(const float4*)&pj[jl+q][h];
            #pragma unroll
            for (int ii = 0; ii < 4; ii++)
                #pragma unroll
                for (int jj = 0; jj < 4; jj++)
                    d[ii][jj] += fabsf(a[ii].x-c[jj].x) + fabsf(a[ii].y-c[jj].y)
                               + fabsf(a[ii].z-c[jj].z) + fabsf(a[ii].w-c[jj].w);
        }
        #pragma unroll
        for (int ii = 0; ii < 4; ii++) {
            float4 v = make_float4(__expf(-d[ii][0]), __expf(-d[ii][1]),
                                   __expf(-d[ii][2]), __expf(-d[ii][3]));
            *(float4*)&Sb[(size_t)(i0+il+ii)*N_ + j0 + jl] = v;
        }
    }
}

__global__ void invd_k(const float* __restrict__ S, float* __restrict__ invd) {
    int tb = blockIdx.x, j = threadIdx.x;
    const float* Sb = S + (size_t)tb * 2 * NN_;
    float s = 0.f;
    #pragma unroll 8
    for (int i = 0; i < N_; i++) s += Sb[(size_t)i*N_ + j];
    invd[tb*N_ + j] = 1.f / s;
}

// ---------------- precompute SGEMM (R11 proven, double-buffered) ----------------
template<int KSPLIT, int XMAP>
__global__ __launch_bounds__(256) void gemm_k(
    const float* __restrict__ A, size_t aStride,
    const float* __restrict__ X, int ldx, size_t xStride,
    const float* __restrict__ invd, int ivStride,
    float* __restrict__ Y, int ldy, size_t yStride)
{
    __shared__ float As[2][16][68];
    __shared__ float Xs[2][16][64];
    const int KL = KSPLIT ? 128 : 256;
    int z = blockIdx.z;
    int b    = KSPLIT ? (z & 7) : z;
    int koff = KSPLIT ? ((z >> 3) * 128) : 0;
    const float* Az = A + (size_t)b * aStride + koff;
    const float* Xz;
    if (XMAP) {
        int t = z >> 3, bb = z & 7;
        Xz = X + ((size_t)(bb*T_ + t)) * N_ * ldx;
    } else {
        Xz = X + (size_t)b * xStride + (size_t)koff * ldx;
    }
    float* Yz = Y + (size_t)z * yStride;
    const float* iv = invd ? (invd + (size_t)(XMAP ? z : b) * ivStride + koff) : nullptr;
    int m0 = blockIdx.y * 64, c0 = blockIdx.x * 64;
    int tid = threadIdx.x;
    int tx = tid & 15, ty = tid >> 4;
    int a_m = tid >> 2, a_k = (tid & 3) * 4;
    int x_k = tid >> 4, x_c = (tid & 15) * 4;
    float acc[4][4] = {};

    float4 av = *(const float4*)&Az[(size_t)(m0 + a_m)*256 + a_k];
    float4 xv = *(const float4*)&Xz[(size_t)(x_k)*ldx + c0 + x_c];
    if (iv) { float s = iv[x_k]; xv.x *= s; xv.y *= s; xv.z *= s; xv.w *= s; }

    int cur = 0;
    for (int k0 = 0; k0 < KL; k0 += 16) {
        As[cur][a_k+0][a_m] = av.x; As[cur][a_k+1][a_m] = av.y;
        As[cur][a_k+2][a_m] = av.z; As[cur][a_k+3][a_m] = av.w;
        *(float4*)&Xs[cur][x_k][x_c] = xv;
        __syncthreads();
        if (k0 + 16 < KL) {
            av = *(const float4*)&Az[(size_t)(m0 + a_m)*256 + k0 + 16 + a_k];
            xv = *(const float4*)&Xz[(size_t)(k0 + 16 + x_k)*ldx + c0 + x_c];
            if (iv) { float s = iv[k0 + 16 + x_k]; xv.x *= s; xv.y *= s; xv.z *= s; xv.w *= s; }
        }
        #pragma unroll
        for (int kk = 0; kk < 16; kk++) {
            float4 a4 = *(const float4*)&As[cur][kk][ty*4];
            float4 x4 = *(const float4*)&Xs[cur][kk][tx*4];
            acc[0][0] += a4.x*x4.x; acc[0][1] += a4.x*x4.y; acc[0][2] += a4.x*x4.z; acc[0][3] += a4.x*x4.w;
            acc[1][0] += a4.y*x4.x; acc[1][1] += a4.y*x4.y; acc[1][2] += a4.y*x4.z; acc[1][3] += a4.y*x4.w;
            acc[2][0] += a4.z*x4.x; acc[2][1] += a4.z*x4.y; acc[2][2] += a4.z*x4.z; acc[2][3] += a4.z*x4.w;
            acc[3][0] += a4.w*x4.x; acc[3][1] += a4.w*x4.y; acc[3][2] += a4.w*x4.z; acc[3][3] += a4.w*x4.w;
        }
        cur ^= 1;
    }
    #pragma unroll
    for (int i = 0; i < 4; i++) {
        float4 v = make_float4(acc[i][0], acc[i][1], acc[i][2], acc[i][3]);
        *(float4*)&Yz[(size_t)(m0 + ty*4 + i)*ldy + c0 + tx*4] = v;
    }
}

// ---------------- layer0 x-part: Px0[tb, row, 0..1] = sup[row,:] @ (invd*x_t) ----------------
__global__ __launch_bounds__(256) void px0_k(const float* __restrict__ S,
    const float* __restrict__ x, const float* __restrict__ invd,
    float* __restrict__ Px0)
{
    __shared__ float xs[256][2];
    int z = blockIdx.x;
    int t = z >> 3, b = z & 7;
    int tid = threadIdx.x;
    const float* xb = x + ((size_t)(b*T_ + t))*N_*2;
    {
        int m = tid;
        float s = invd[z*N_ + m];
        xs[m][0] = xb[m*2+0]*s;
        xs[m][1] = xb[m*2+1]*s;
    }
    __syncthreads();
    int w = tid >> 5, lane = tid & 31;
    int row = blockIdx.y * 8 + w;
    const float* Ar = S + (size_t)z*2*NN_ + (size_t)row*256;
    float a0 = 0.f, a1 = 0.f;
    #pragma unroll
    for (int m = lane; m < 256; m += 32) {
        float a = Ar[m];
        a0 += a*xs[m][0];
        a1 += a*xs[m][1];
    }
    #pragma unroll
    for (int off = 16; off; off >>= 1) {
        a0 += __shfl_down_sync(0xffffffff, a0, off);
        a1 += __shfl_down_sync(0xffffffff, a1, off);
    }
    if (!lane) {
        Px0[(size_t)z*1024 + row*2 + 0] = a0;
        Px0[(size_t)z*1024 + row*2 + 1] = a1;
    }
}

// ================= persistent recurrent kernel =================

__device__ __forceinline__ void gridbar() {
    __syncthreads();
    if (threadIdx.x == 0) {
        unsigned s = *(volatile unsigned*)&g_sense;
        __threadfence();
        if (atomicAdd(&g_count, 1u) == NBLK - 1u) {
            g_count = 0;
            __threadfence();
            *(volatile unsigned*)&g_sense = s + 1u;
        } else {
            while (*(volatile unsigned*)&g_sense == s) __nanosleep(32);
        }
        __threadfence();
    }
    __syncthreads();
}

// 32-row tile GEMM, K=128 segment (R14 body; X via __ldcg)
__device__ __forceinline__ void dgemm32(
    const float* __restrict__ Az,   // + b*2NND + koff   (lda = 256)
    const float* __restrict__ Xz,   // + b*16384 + koff*64 (ldx = 64)
    const float* __restrict__ iv,   // + koff
    float* __restrict__ Yz,         // + kz*PART_ + b*32768
    int m0, float* sm)
{
    float* As = sm;          // [2][16][34]
    float* Xs = sm + 1088;   // [2][16][64]
    int tid = threadIdx.x;
    int tx = tid & 15, ty = tid >> 4;
    int a_m = tid >> 3, a_k = (tid & 7) * 2;
    int x_k = tid >> 4, x_c = (tid & 15) * 4;
    float acc[2][4] = {};

    float2 av = *(const float2*)&Az[(size_t)(m0 + a_m)*256 + a_k];
    float4 xv = __ldcg((const float4*)&Xz[(size_t)x_k*64 + x_c]);
    { float s = iv[x_k]; xv.x *= s; xv.y *= s; xv.z *= s; xv.w *= s; }

    int cur = 0;
    #pragma unroll 1
    for (int k0 = 0; k0 < 128; k0 += 16) {
        As[cur*544 + (a_k+0)*34 + a_m] = av.x;
        As[cur*544 + (a_k+1)*34 + a_m] = av.y;
        *(float4*)&Xs[cur*1024 + x_k*64 + x_c] = xv;
        __syncthreads();
        if (k0 + 16 < 128) {
            av = *(const float2*)&Az[(size_t)(m0 + a_m)*256 + k0 + 16 + a_k];
            xv = __ldcg((const float4*)&Xz[(size_t)(k0 + 16 + x_k)*64 + x_c]);
            float s = iv[k0 + 16 + x_k]; xv.x *= s; xv.y *= s; xv.z *= s; xv.w *= s;
        }
        #pragma unroll
        for (int kk = 0; kk < 16; kk++) {
            float a0 = As[cur*544 + kk*34 + ty*2];
            float a1 = As[cur*544 + kk*34 + ty*2 + 1];
            float4 x4 = *(const float4*)&Xs[cur*1024 + kk*64 + tx*4];
            acc[0][0] += a0*x4.x; acc[0][1] += a0*x4.y; acc[0][2] += a0*x4.z; acc[0][3] += a0*x4.w;
            acc[1][0] += a1*x4.x; acc[1][1] += a1*x4.y; acc[1][2] += a1*x4.z; acc[1][3] += a1*x4.w;
        }
        cur ^= 1;
    }
    #pragma unroll
    for (int i = 0; i < 2; i++) {
        float4 v = make_float4(acc[i][0], acc[i][1], acc[i][2], acc[i][3]);
        *(float4*)&Yz[(size_t)(m0 + ty*2 + i)*64 + tx*4] = v;
    }
}

// per-node MLP with fused GRU epilogue (R11 body; cross-phase reads via __ldcg)
template<int COUT, int NB, int MODE, int CS>
__device__ __forceinline__ void dmlp(
    int n,
    const float* __restrict__ ys,
    const float* __restrict__ Ppa_t,
    const float* __restrict__ Px_t,
    const float* __restrict__ W, const float* __restrict__ bias,
    const float* __restrict__ sp, const float* __restrict__ pa_t,
    const float* __restrict__ rbuf,
    float* __restrict__ o1, float* __restrict__ o2, float* __restrict__ hid,
    float* Xs)
{
    constexpr int K2  = 2*CS;
    constexpr int XLD = CS - 64;
    int tid = threadIdx.x;
    for (int idx = tid; idx < 8*K2; idx += 256) {
        int b = idx / K2, r = idx - b*K2;
        int k = (r >= CS) ? 1 : 0;
        int c = r - k*CS;
        float v;
        size_t base = ((size_t)(b*2 + k)*256 + n)*64;
        if (c < 64) {
            v = __ldcg(ys + base + c) + __ldcg(ys + PART_ + base + c);
            if (MODE == 0) v += Ppa_t[base + c];
        } else {
            v = __ldcg(Px_t + ((size_t)(b*2 + k)*256 + n)*XLD + (c - 64));
        }
        Xs[b*K2 + r] = v;
    }
    __syncthreads();
    constexpr int GROUPS = 256 / COUT;
    int o = tid % COUT;
    int bb0 = tid / COUT;
    float acc[NB];
    #pragma unroll
    for (int g = 0; g < NB; g++) acc[g] = 0.f;
    const float* Wn = W + (size_t)n * K2 * COUT + o;

    int kk = 0;
    #pragma unroll 1
    for (; kk + 8 <= K2; kk += 8) {
        float w[8];
        #pragma unroll
        for (int q = 0; q < 8; q++)
            w[q] = __ldg(Wn + (size_t)(kk + q)*COUT);
        #pragma unroll
        for (int q = 0; q < 8; q++) {
            #pragma unroll
            for (int g = 0; g < NB; g++)
                acc[g] += Xs[(bb0 + g*GROUPS)*K2 + kk + q] * w[q];
        }
    }
    #pragma unroll 1
    for (; kk < K2; kk++) {
        float w = __ldg(Wn + (size_t)kk*COUT);
        #pragma unroll
        for (int g = 0; g < NB; g++)
            acc[g] += Xs[(bb0 + g*GROUPS)*K2 + kk] * w;
    }

    float bv = bias[n*COUT + o];
    #pragma unroll
    for (int g = 0; g < NB; g++) {
        int b = bb0 + g*GROUPS;
        size_t bn = (size_t)b*256 + n;
        size_t pbn = (size_t)b*(T_*N_*H_) + (size_t)n*64;
        if (MODE == 0) {
            float val = 1.f / (1.f + __expf(-(acc[g] + bv)));
            if (o < 64) o1[bn*64 + o] = val * (__ldcg(sp + bn*64 + o) + pa_t[pbn + o]);
            else        o2[bn*64 + (o - 64)] = val;
        } else {
            float hc = tanhf(acc[g] + bv);
            float se = __ldcg(sp + bn*64 + o) + pa_t[pbn + o];
            float rr = __ldcg(rbuf + bn*64 + o);
            float s  = rr*se + (1.f - rr)*hc;
            o1[bn*64 + o] = s;
            o2[pbn + o]   = s;
            if (hid) hid[bn*64 + o] = s;
        }
    }
}

template<int LAYER>
__global__ __launch_bounds__(256, 2) void loop_k(
    const float* __restrict__ isti, const float* __restrict__ pa,
    float* __restrict__ seqout, float* __restrict__ hid)
{
    __shared__ float sm[3136];
    constexpr int CS = LAYER ? 128 : 66;
    constexpr int XLD = CS - 64;
    const float* Wg = LAYER ? g_Wg1 : g_Wg0;
    const float* Bg = LAYER ? g_Bg1 : g_Bg0;
    const float* Wu = LAYER ? g_Wu1 : g_Wu0;
    const float* Bu = LAYER ? g_Bu1 : g_Bu0;
    const float* Px = LAYER ? g_Px1 : g_Px0;

    int bid = blockIdx.x;
    int z = bid >> 4, mt = bid & 15;
    int b = z & 7, kz = z >> 3;
    int koff = kz * 128;
    int m0 = mt * 32;

    for (int t = 0; t < T_; t++) {
        const float* sp  = t ? (const float*)g_state : isti;
        const float* Sb  = g_S + (size_t)t*8*2*NND;
        const float* ivt = g_invd + (size_t)t*8*256;
        const float* pat = pa + (size_t)t*N_*H_;
        const float* Ppt = g_Ppa + (size_t)t*8*32768;
        const float* Pxt = Px + (size_t)t*8*512*XLD;
        float* hidt = (t == T_-1) ? hid : nullptr;

        // P1: gate GEMM on state columns (256 tiles)
        dgemm32(Sb + (size_t)b*2*NND + koff,
                sp + (size_t)b*16384 + (size_t)koff*64,
                ivt + b*256 + koff,
                g_ys + (size_t)kz*PART_ + (size_t)b*32768,
                m0, sm);
        gridbar();
        // P2: gate MLP (1 node/block)
        dmlp<128,4,0,CS>(bid, g_ys, Ppt, Pxt, Wg, Bg, sp, pat, nullptr,
                         g_zs, g_rbuf, nullptr, sm);
        gridbar();
        // P3: update GEMM on zs
        dgemm32(Sb + (size_t)b*2*NND + koff,
                (const float*)g_zs + (size_t)b*16384 + (size_t)koff*64,
                ivt + b*256 + koff,
                g_us + (size_t)kz*PART_ + (size_t)b*32768,
                m0, sm);
        gridbar();
        // P4: update MLP
        dmlp<64,2,1,CS>(bid, g_us, nullptr, Pxt, Wu, Bu, sp, pat, g_rbuf,
                        g_state, seqout + (size_t)t*N_*H_, hidt, sm);
        gridbar();
    }
}

static float* symaddr(const void* sym) {
    void* p = nullptr;
    cudaGetSymbolAddress(&p, sym);
    return (float*)p;
}

extern "C" void kernel_launch(void* const* d_in, const int* in_sizes, int n_in,
                              void* d_out, int out_size) {
    const float* x    = (const float*)d_in[0];
    const float* ist  = (const float*)d_in[1];
    const float* E    = (const float*)d_in[2];
    const float* pa   = (const float*)d_in[3];
    const float* gw0  = (const float*)d_in[4];
    const float* gb0  = (const float*)d_in[5];
    const float* uw0  = (const float*)d_in[6];
    const float* ub0  = (const float*)d_in[7];
    const float* gw1  = (const float*)d_in[8];
    const float* gb1  = (const float*)d_in[9];
    const float* uw1  = (const float*)d_in[10];
    const float* ub1  = (const float*)d_in[11];
    float* out = (float*)d_out;

    float* adj  = symaddr(g_adj);
    float* S    = symaddr(g_S);
    float* invd = symaddr(g_invd);
    float* Wg0  = symaddr(g_Wg0);
    float* Wu0  = symaddr(g_Wu0);
    float* Wg1  = symaddr(g_Wg1);
    float* Wu1  = symaddr(g_Wu1);
    float* Bg0  = symaddr(g_Bg0);
    float* Bu0  = symaddr(g_Bu0);
    float* Bg1  = symaddr(g_Bg1);
    float* Bu1  = symaddr(g_Bu1);
    float* Ppa  = symaddr(g_Ppa);
    float* Px0  = symaddr(g_Px0);
    float* Px1  = symaddr(g_Px1);
    float* seq0 = symaddr(g_seq0);

    const size_t ZY = (size_t)2*256*64;
    float* hid0 = out + (size_t)B_*T_*N_*H_;
    float* hid1 = hid0 + (size_t)B_*N_*H_;

    // -------- precompute (wide, parallel kernels) --------
    adj_k<<<256, 256>>>(E, adj);
    wexpand_all<<<dim3(256, 4), 128>>>(E, gw0, uw0, gw1, uw1, Wg0, Wu0, Wg1, Wu1);
    bexpand_all<<<dim3(256, 4), 128>>>(E, gb0, ub0, gb1, ub1, Bg0, Bu0, Bg1, Bu1);
    sker_k<<<dim3(TB_, 4), 256>>>(pa, S);
    invd_k<<<TB_, 256>>>(S, invd);
    // A2[tb] = adj @ S[tb]  -> slot 1
    gemm_k<0,0><<<dim3(4, 4, TB_), 256>>>(adj, 0, S, 256, 2*NN_, nullptr, 0,
                                          S + NN_, 256, 2*NN_);
    // Ppa[tb] = [S;A2] @ (invd * pa_t)
    gemm_k<0,1><<<dim3(1, 8, TB_), 256>>>(S, 2*NN_, pa, 64, 0, invd, N_,
                                          Ppa, 64, ZY);
    // Px0[tb] = [S;A2] @ (invd * x_t)
    px0_k<<<dim3(TB_, 64), 256>>>(S, x, invd, Px0);

    // -------- layer 0 (persistent) --------
    loop_k<0><<<NBLK, 256>>>(ist, pa, seq0, hid0);

    // Px1[tb] = [S;A2] @ (invd * seq0_t)  (wide, parallel over all t)
    gemm_k<0,1><<<dim3(1, 8, TB_), 256>>>(S, 2*NN_, seq0, 64, 0, invd, N_,
                                          Px1, 64, ZY);

    // -------- layer 1 (persistent) --------
    loop_k<1><<<NBLK, 256>>>(ist + (size_t)B_*N_*H_, pa, out, hid1);
}